// round 5
// baseline (speedup 1.0000x reference)
#include <cuda_runtime.h>

#define OUT_H      8
#define MAX_WIDTH  384
#define FH         160
#define FW         160
#define CCH        32
#define NUM_BOXES  256
#define NF4        (MAX_WIDTH * (CCH / 4))   // 3072 float4 per (box,row) strip

// One block per (box,row) strip. Phase 1 computes per-pixel bilinear weights
// and corner base-indices ONCE into smem; phase 2 streams 3072 float4 outputs
// with zero redundant scalar math and no divergence.

__global__ __launch_bounds__(256)
void rotate_bilinear_kernel(const float* __restrict__ feat,
                            const float* __restrict__ theta,
                            const int*   __restrict__ box_info,
                            float4*      __restrict__ out)
{
    __shared__ float4 sw[MAX_WIDTH];   // wa, wb, wc, wd
    __shared__ int4   si[MAX_WIDTH];   // float4-unit base indices of 4 corners

    const int t   = blockIdx.x;        // b*OUT_H + row
    const int b   = t >> 3;
    const int row = t & (OUT_H - 1);
    const int tid = threadIdx.x;

    const int img = __ldg(&box_info[2 * b]);
    const int bw  = __ldg(&box_info[2 * b + 1]);

    const float* th = theta + 6 * b;
    const float t0 = __ldg(th + 0), t1 = __ldg(th + 1), t2 = __ldg(th + 2);
    const float t3 = __ldg(th + 3), t4 = __ldg(th + 4), t5 = __ldg(th + 5);

    const float rcp2 = __fdividef(2.0f, (float)bw - 1.0f);
    const float yt   = -1.0f + 2.0f * (float)row * (1.0f / (float)(OUT_H - 1));
    const float cx   = t1 * yt + t2;
    const float cy   = t4 * yt + t5;

    // ---- Phase 1: per-pixel weights + indices (once per pixel) ----
    for (int p = tid; p < MAX_WIDTH; p += 256) {
        float4 w  = make_float4(0.f, 0.f, 0.f, 0.f);
        int4   ii = make_int4(0, 0, 0, 0);
        if (p < bw) {
            const float xt = (float)p * rcp2 - 1.0f;
            const float x  = (t0 * xt + cx + 1.0f) * ((float)FW * 0.5f);
            const float y  = (t3 * xt + cy + 1.0f) * ((float)FH * 0.5f);
            const int x0i = (int)floorf(x), y0i = (int)floorf(y);
            const int x0c = min(max(x0i,     0), FW - 1);
            const int x1c = min(max(x0i + 1, 0), FW - 1);
            const int y0c = min(max(y0i,     0), FH - 1);
            const int y1c = min(max(y0i + 1, 0), FH - 1);
            const float dx0 = (float)x1c - x, dx1 = x - (float)x0c;
            const float dy0 = (float)y1c - y, dy1 = y - (float)y0c;
            w = make_float4(dx0 * dy0, dx0 * dy1, dx1 * dy0, dx1 * dy1);
            const int rA = (img * FH + y0c) * FW;
            const int rB = (img * FH + y1c) * FW;
            ii = make_int4((rA + x0c) * (CCH / 4),
                           (rB + x0c) * (CCH / 4),
                           (rA + x1c) * (CCH / 4),
                           (rB + x1c) * (CCH / 4));
        }
        sw[p] = w;
        si[p] = ii;
    }
    __syncthreads();

    // ---- Phase 2: stream 3072 float4 outputs ----
    const float4* __restrict__ f4 = (const float4*)feat;
    float4* __restrict__ ob = out + (long)t * NF4;

    #pragma unroll 4
    for (int it = 0; it < NF4 / 256; ++it) {
        const int idx = it * 256 + tid;
        const int p   = idx >> 3;          // pixel (column)
        const int c4  = idx & 7;           // float4 slot within 32 channels

        const float4 w  = sw[p];
        const int4   ii = si[p];

        const float4 Ia = __ldg(f4 + ii.x + c4);
        const float4 Ib = __ldg(f4 + ii.y + c4);
        const float4 Ic = __ldg(f4 + ii.z + c4);
        const float4 Id = __ldg(f4 + ii.w + c4);

        float4 o;
        o.x = w.x * Ia.x + w.y * Ib.x + w.z * Ic.x + w.w * Id.x;
        o.y = w.x * Ia.y + w.y * Ib.y + w.z * Ic.y + w.w * Id.y;
        o.z = w.x * Ia.z + w.y * Ib.z + w.z * Ic.z + w.w * Id.z;
        o.w = w.x * Ia.w + w.y * Ib.w + w.z * Ic.w + w.w * Id.w;

        __stcs(ob + idx, o);
    }
}

extern "C" void kernel_launch(void* const* d_in, const int* in_sizes, int n_in,
                              void* d_out, int out_size)
{
    const float* feat  = (const float*)d_in[0];   // [8,160,160,32] f32
    const float* theta = (const float*)d_in[1];   // [256,6] f32
    const int*   binfo = (const int*)d_in[2];     // [256,2] i32

    const int grid = NUM_BOXES * OUT_H;           // 2048 blocks
    rotate_bilinear_kernel<<<grid, 256>>>(feat, theta, binfo, (float4*)d_out);
}

// round 6
// speedup vs baseline: 1.3894x; 1.3894x over previous
#include <cuda_runtime.h>

#define OUT_H      8
#define MAX_WIDTH  384
#define QW         96            // MAX_WIDTH / 4
#define FH         160
#define FW         160
#define CCH        32
#define NUM_BOXES  256

// 8 threads per pixel (one float4 each -> 128B-contiguous gathers, 4 L1
// wavefronts per LDG.128). Each thread handles FOUR pixels of the same
// (box,row): cols c, c+96, c+192, c+288. Transform folded to x=A*p+B.

__global__ __launch_bounds__(256)
void rotate_bilinear_kernel(const float* __restrict__ feat,
                            const float* __restrict__ theta,
                            const int*   __restrict__ box_info,
                            float4*      __restrict__ out)
{
    const int tid = blockIdx.x * blockDim.x + threadIdx.x;

    const int c4  = tid & 7;          // float4 slot within 32 channels
    const int p   = tid >> 3;         // (box, row, quartercol)
    const int col = p % QW;           // base column; pixels at col + k*96
    const int t   = p / QW;
    const int row = t & (OUT_H - 1);
    const int b   = t >> 3;           // OUT_H == 8

    const int img = __ldg(&box_info[2 * b]);
    const int bw  = __ldg(&box_info[2 * b + 1]);

    const float* th = theta + 6 * b;
    const float t0 = __ldg(th + 0), t1 = __ldg(th + 1), t2 = __ldg(th + 2);
    const float t3 = __ldg(th + 3), t4 = __ldg(th + 4), t5 = __ldg(th + 5);

    const float rcp2 = __fdividef(2.0f, (float)bw - 1.0f);
    const float yt   = -1.0f + 2.0f * (float)row * (1.0f / (float)(OUT_H - 1));

    // x = ((t0*(p*rcp2-1) + t1*yt + t2) + 1) * 80  ->  x = Ax*p + Bx
    const float Ax = t0 * rcp2 * ((float)FW * 0.5f);
    const float Bx = (t1 * yt + t2 - t0 + 1.0f) * ((float)FW * 0.5f);
    const float Ay = t3 * rcp2 * ((float)FH * 0.5f);
    const float By = (t4 * yt + t5 - t3 + 1.0f) * ((float)FH * 0.5f);

    const float4* __restrict__ f4 = (const float4*)feat;
    const long opix = (long)(t * MAX_WIDTH + col);   // first pixel's index

    #pragma unroll
    for (int k = 0; k < 4; ++k) {
        const int pc = col + k * QW;
        float4 o = make_float4(0.f, 0.f, 0.f, 0.f);

        if (pc < bw) {
            const float pf = (float)pc;
            const float x  = fmaf(Ax, pf, Bx);
            const float y  = fmaf(Ay, pf, By);

            const int x0i = __float2int_rd(x);
            const int y0i = __float2int_rd(y);
            const int x0c = min(max(x0i,     0), FW - 1);
            const int x1c = min(max(x0i + 1, 0), FW - 1);
            const int y0c = min(max(y0i,     0), FH - 1);
            const int y1c = min(max(y0i + 1, 0), FH - 1);

            const float dx0 = (float)x1c - x, dx1 = x - (float)x0c;
            const float dy0 = (float)y1c - y, dy1 = y - (float)y0c;
            const float wa = dx0 * dy0, wb = dx0 * dy1;
            const float wc = dx1 * dy0, wd = dx1 * dy1;

            const int rA = (img * FH + y0c) * FW;
            const int rB = (img * FH + y1c) * FW;

            const float4 Ia = __ldg(f4 + (rA + x0c) * (CCH / 4) + c4);
            const float4 Ib = __ldg(f4 + (rB + x0c) * (CCH / 4) + c4);
            const float4 Ic = __ldg(f4 + (rA + x1c) * (CCH / 4) + c4);
            const float4 Id = __ldg(f4 + (rB + x1c) * (CCH / 4) + c4);

            o.x = wa * Ia.x + wb * Ib.x + wc * Ic.x + wd * Id.x;
            o.y = wa * Ia.y + wb * Ib.y + wc * Ic.y + wd * Id.y;
            o.z = wa * Ia.z + wb * Ib.z + wc * Ic.z + wd * Id.z;
            o.w = wa * Ia.w + wb * Ib.w + wc * Ic.w + wd * Id.w;
        }

        __stcs(out + (opix + k * QW) * (CCH / 4) + c4, o);
    }
}

extern "C" void kernel_launch(void* const* d_in, const int* in_sizes, int n_in,
                              void* d_out, int out_size)
{
    const float* feat  = (const float*)d_in[0];   // [8,160,160,32] f32
    const float* theta = (const float*)d_in[1];   // [256,6] f32
    const int*   binfo = (const int*)d_in[2];     // [256,2] i32

    const int total_threads = NUM_BOXES * OUT_H * QW * 8; // 1,572,864
    const int block = 256;
    const int grid  = total_threads / block;      // 6144

    rotate_bilinear_kernel<<<grid, block>>>(feat, theta, binfo, (float4*)d_out);
}